// round 1
// baseline (speedup 1.0000x reference)
#include <cuda_runtime.h>

// out[b,t,c] = (1/(t+1)) * sum_{j<=t} x[b,j,c]
// (weights matrix is the causal uniform-average operator; input d_in[1] unused)

#define BATCH   16
#define TLEN    8192
#define CH      64
#define CHUNK   128
#define NCHUNK  (TLEN / CHUNK)   // 64

// scratch: per-(batch, chunk, channel) partial sums -> exclusive prefixes
__device__ float g_partial[BATCH][NCHUNK][CH];

// K1: each block = (chunk, batch); thread c sums its channel over 128 rows.
__global__ void __launch_bounds__(CH) k_partial(const float* __restrict__ x) {
    const int chunk = blockIdx.x;
    const int b     = blockIdx.y;
    const int c     = threadIdx.x;
    const float* p = x + ((size_t)b * TLEN + (size_t)chunk * CHUNK) * CH + c;
    float s = 0.0f;
#pragma unroll 8
    for (int i = 0; i < CHUNK; i++) s += p[(size_t)i * CH];
    g_partial[b][chunk][c] = s;
}

// K2: 1024 lanes (b,c), each does a sequential exclusive scan over 64 chunks.
__global__ void __launch_bounds__(BATCH * CH) k_scan() {
    const int tid = threadIdx.x;           // 0..1023
    const int b = tid / CH, c = tid % CH;
    float run = 0.0f;
#pragma unroll
    for (int k = 0; k < NCHUNK; k++) {
        const float v = g_partial[b][k][c];
        g_partial[b][k][c] = run;
        run += v;
    }
}

// K3: re-read x (L2-resident after K1), add chunk prefix, running cumsum,
// scale by 1/(t+1), write out.
__global__ void __launch_bounds__(CH) k_out(const float* __restrict__ x,
                                            float* __restrict__ out) {
    const int chunk = blockIdx.x;
    const int b     = blockIdx.y;
    const int c     = threadIdx.x;
    const size_t base = ((size_t)b * TLEN + (size_t)chunk * CHUNK) * CH + c;
    const float* p = x   + base;
    float*       o = out + base;
    float acc = g_partial[b][chunk][c];
    const int t0 = chunk * CHUNK;
#pragma unroll 8
    for (int i = 0; i < CHUNK; i++) {
        acc += p[(size_t)i * CH];
        o[(size_t)i * CH] = acc * (1.0f / (float)(t0 + i + 1));
    }
}

extern "C" void kernel_launch(void* const* d_in, const int* in_sizes, int n_in,
                              void* d_out, int out_size) {
    const float* x = (const float*)d_in[0];   // [16, 8192, 64] fp32
    float* out = (float*)d_out;               // [16, 8192, 64] fp32

    dim3 grid(NCHUNK, BATCH);
    k_partial<<<grid, CH>>>(x);
    k_scan<<<1, BATCH * CH>>>();
    k_out<<<grid, CH>>>(x, out);
}

// round 2
// speedup vs baseline: 1.2675x; 1.2675x over previous
#include <cuda_runtime.h>

// out[b,t,c] = (1/(t+1)) * sum_{j<=t} x[b,j,c]
// weights input (d_in[1]) is the causal uniform-average operator -> unused.

#define BATCH   16
#define TLEN    8192
#define CH      64
#define C4N     16           // float4 per row (64 ch / 4)
#define CHUNK   128          // rows per chunk
#define NCHUNK  (TLEN/CHUNK) // 64
#define RS      16           // row slices per chunk
#define RPT     (CHUNK/RS)   // 8 rows per thread
#define NTHR    (C4N*RS)     // 256 threads/block

__device__ float4 g_agg[BATCH][NCHUNK][C4N];

__device__ __forceinline__ void f4acc(float4& a, const float4 v) {
    a.x += v.x; a.y += v.y; a.z += v.z; a.w += v.w;
}

// K1: per-(b,chunk) aggregate of 128 rows, float4-vectorized.
__global__ void __launch_bounds__(NTHR) k_agg(const float4* __restrict__ x4) {
    const int chunk = blockIdx.x, b = blockIdx.y;
    const int c4 = threadIdx.x & 15, rs = threadIdx.x >> 4;
    const float4* p = x4 + ((size_t)(b * TLEN + chunk * CHUNK + rs * RPT)) * C4N + c4;
    float4 s = make_float4(0.f, 0.f, 0.f, 0.f);
#pragma unroll
    for (int i = 0; i < RPT; i++) f4acc(s, p[(size_t)i * C4N]);
    __shared__ float4 sm[RS][C4N];
    sm[rs][c4] = s;
    __syncthreads();
    if (rs == 0) {
        float4 a = sm[0][c4];
#pragma unroll
        for (int r = 1; r < RS; r++) f4acc(a, sm[r][c4]);
        g_agg[b][chunk][c4] = a;
    }
}

// K2: exclusive scan of 64 chunk aggregates per (b, c4) lane. 256 lanes, 1 block.
__global__ void __launch_bounds__(BATCH * C4N) k_scan() {
    const int b = threadIdx.x >> 4, c4 = threadIdx.x & 15;
    float4 run = make_float4(0.f, 0.f, 0.f, 0.f);
#pragma unroll
    for (int k = 0; k < NCHUNK; k++) {
        const float4 v = g_agg[b][k][c4];
        g_agg[b][k][c4] = run;
        f4acc(run, v);
    }
}

// K3: load 8 rows into regs, block-local hierarchical scan, scale, store.
__global__ void __launch_bounds__(NTHR) k_out(const float4* __restrict__ x4,
                                              float4* __restrict__ o4) {
    const int chunk = blockIdx.x, b = blockIdx.y;
    const int c4 = threadIdx.x & 15, rs = threadIdx.x >> 4;
    const size_t base = ((size_t)(b * TLEN + chunk * CHUNK + rs * RPT)) * C4N + c4;

    float4 rows[RPT];
#pragma unroll
    for (int i = 0; i < RPT; i++) rows[i] = x4[base + (size_t)i * C4N];

    // thread partial
    float4 tp = rows[0];
#pragma unroll
    for (int i = 1; i < RPT; i++) f4acc(tp, rows[i]);

    __shared__ float4 sm[RS][C4N];
    sm[rs][c4] = tp;
    __syncthreads();

    // exclusive prefix: chunk prefix + sum of earlier row-slices
    float4 acc = g_agg[b][chunk][c4];
    for (int r = 0; r < rs; r++) f4acc(acc, sm[r][c4]);

    const int t0 = chunk * CHUNK + rs * RPT;
#pragma unroll
    for (int i = 0; i < RPT; i++) {
        f4acc(acc, rows[i]);
        const float inv = __fdividef(1.0f, (float)(t0 + i + 1));
        float4 o;
        o.x = acc.x * inv; o.y = acc.y * inv; o.z = acc.z * inv; o.w = acc.w * inv;
        o4[base + (size_t)i * C4N] = o;
    }
}

extern "C" void kernel_launch(void* const* d_in, const int* in_sizes, int n_in,
                              void* d_out, int out_size) {
    const float4* x4 = (const float4*)d_in[0];   // [16, 8192, 64] fp32
    float4* o4 = (float4*)d_out;

    dim3 grid(NCHUNK, BATCH);
    k_agg<<<grid, NTHR>>>(x4);
    k_scan<<<1, BATCH * C4N>>>();
    k_out<<<grid, NTHR>>>(x4, o4);
}

// round 5
// speedup vs baseline: 2.4241x; 1.9125x over previous
#include <cuda_runtime.h>
#include <cstdint>

// out[b,t,c] = (1/(t+1)) * sum_{j<=t} x[b,j,c]   (weights input unused)

#define BATCH   16
#define TLEN    8192
#define C4N     16           // float4 per row
#define CHUNK   128
#define NCHUNK  (TLEN/CHUNK) // 64
#define RS      16
#define RPT     (CHUNK/RS)   // 8 rows/thread
#define NTHR    (C4N*RS)     // 256

__device__ float4 g_agg[BATCH][NCHUNK][C4N];
__device__ int    g_flag[BATCH][NCHUNK][C4N];   // zero-init at module load

__device__ __forceinline__ void f4acc(float4& a, const float4 v) {
    a.x += v.x; a.y += v.y; a.z += v.z; a.w += v.w;
}

__device__ __forceinline__ void st_release(int* p, int v) {
    asm volatile("st.global.release.gpu.b32 [%0], %1;" :: "l"(p), "r"(v) : "memory");
}
__device__ __forceinline__ int ld_acquire(const int* p) {
    int v;
    asm volatile("ld.global.acquire.gpu.b32 %0, [%1];" : "=r"(v) : "l"(p) : "memory");
    return v;
}

__global__ void __launch_bounds__(NTHR) k_fused(const float4* __restrict__ x4,
                                                float4* __restrict__ o4) {
    const int chunk = blockIdx.x, b = blockIdx.y;
    const int c4 = threadIdx.x & 15, rs = threadIdx.x >> 4;
    const size_t base = ((size_t)(b * TLEN + chunk * CHUNK + rs * RPT)) * C4N + c4;

    // 1) load slab rows into registers (8 x 16B per thread, front-batched MLP)
    float4 rows[RPT];
#pragma unroll
    for (int i = 0; i < RPT; i++) rows[i] = x4[base + (size_t)i * C4N];

    // 2) thread partial over its 8 rows
    float4 tp = rows[0];
#pragma unroll
    for (int i = 1; i < RPT; i++) f4acc(tp, rows[i]);

    __shared__ float4 sm[RS][C4N];    // slice partials
    __shared__ float4 smp[RS][C4N];   // predecessor partial sums
    sm[rs][c4] = tp;
    __syncthreads();

    // 3) publish this chunk's aggregate (rs==0 threads, one per c4 lane)
    if (rs == 0) {
        float4 a = sm[0][c4];
#pragma unroll
        for (int r = 1; r < RS; r++) f4acc(a, sm[r][c4]);
        g_agg[b][chunk][c4] = a;
        st_release(&g_flag[b][chunk][c4], 1);
    }

    // 4) cooperative flat lookback: thread (c4,rs) sums chunks j == rs (mod 16)
    float4 pre = make_float4(0.f, 0.f, 0.f, 0.f);
    for (int j = rs; j < chunk; j += RS) {
        int spin = 0;
        while (ld_acquire(&g_flag[b][j][c4]) == 0) {
            if (spin < 64) spin++;
            __nanosleep(spin < 64 ? 32 : 256);
        }
        f4acc(pre, g_agg[b][j][c4]);
    }
    smp[rs][c4] = pre;
    __syncthreads();

    // 5) exclusive prefix = all predecessor chunks + earlier row slices
    float4 acc = smp[0][c4];
#pragma unroll
    for (int r = 1; r < RS; r++) f4acc(acc, smp[r][c4]);
    for (int r = 0; r < rs; r++) f4acc(acc, sm[r][c4]);

    // 6) in-register cumsum, scale by 1/(t+1), store
    const int t0 = chunk * CHUNK + rs * RPT;
#pragma unroll
    for (int i = 0; i < RPT; i++) {
        f4acc(acc, rows[i]);
        const float inv = __fdividef(1.0f, (float)(t0 + i + 1));
        float4 o;
        o.x = acc.x * inv; o.y = acc.y * inv; o.z = acc.z * inv; o.w = acc.w * inv;
        o4[base + (size_t)i * C4N] = o;
    }
}

extern "C" void kernel_launch(void* const* d_in, const int* in_sizes, int n_in,
                              void* d_out, int out_size) {
    const float4* x4 = (const float4*)d_in[0];   // [16, 8192, 64] fp32
    float4* o4 = (float4*)d_out;
    dim3 grid(NCHUNK, BATCH);
    k_fused<<<grid, NTHR>>>(x4, o4);
}